// round 2
// baseline (speedup 1.0000x reference)
#include <cuda_runtime.h>
#include <math.h>

#define NB   512
#define TT   64
#define NLc  32
#define LATc 64
#define HIDc 128
#define G3   384
#define DIN  65
#define MAXG 160

__device__ float g_gix[TT*NB*G3];
__device__ float g_z0 [NB*LATc];
__device__ float g_ys [MAXG*NB*LATc];
__device__ float g_grid[MAXG];
__device__ int   g_niters;
__device__ int   g_mask_mode;
__device__ float g_klrow[NB];
__device__ float g_rpart[4096];
__device__ int   g_ncnt[4096];

__device__ __forceinline__ float sigmoidf_(float x){ return 1.0f/(1.0f+expf(-x)); }
__device__ __forceinline__ float mask_at(const void* m, int idx, int mode){
    if (mode==0) return (float)((const unsigned char*)m)[idx];
    if (mode==1) return (float)((const int*)m)[idx];
    return ((const float*)m)[idx];
}

// ---- K0: grid construction (float64, numpy-matching) + mask dtype detect ----
__global__ void k0_grid(const int* __restrict__ tp, const void* __restrict__ msk){
    __shared__ int smn[NB], smx[NB];
    int b = threadIdx.x;
    smn[b] = tp[b*TT];
    smx[b] = tp[b*TT + TT-1];
    __syncthreads();
    if (b == 0){
        int mn = smn[0], mx = smx[0];
        for (int i = 1; i < NB; i++){ mn = min(mn, smn[i]); mx = max(mx, smx[i]); }
        float q0 = (float)mn / 365.0f, q1 = (float)mx / 365.0f;
        double t0 = (double)q0, t1 = (double)q1;
        int n = (int)ceil((t1 - t0)/0.05 + 1.0);
        if (n < 2) n = 2;
        if (n > MAXG) n = MAXG;
        for (int i = 0; i < n; i++){
            double g = (double)i*0.05 + t0;
            if (i == n-1 && g > t1) g = t1;
            g_grid[i] = (float)g;
        }
        g_niters = n;
    }
    if (b == 1){
        const unsigned int* mw = (const unsigned int*)msk;
        bool alli = true, allf = true;
        for (int i = 0; i < 64; i++){
            unsigned v = mw[i];
            if (v != 0u && v != 1u) alli = false;
            if (v != 0u && v != 0x3f800000u) allf = false;
        }
        g_mask_mode = alli ? 1 : (allf ? 2 : 0);
    }
}

// ---- K1: gix[s][b][:] = inp(b, 63-s) @ Wih + bih ----
__global__ void k1_ingemm(const float* __restrict__ obs, const void* __restrict__ msk,
                          const int* __restrict__ tp, const float* __restrict__ Wih,
                          const float* __restrict__ bih){
    extern __shared__ float sm[];
    float* Wsh = sm;              // 65*384
    float* inp = sm + DIN*G3;     // [k][i], 65*64
    int tid = threadIdx.x;        // 384
    int mode = g_mask_mode;
    for (int idx = tid; idx < DIN*G3; idx += G3) Wsh[idx] = Wih[idx];
    int m0 = blockIdx.x * 64;
    for (int idx = tid; idx < DIN*64; idx += G3){
        int k = idx >> 6, i = idx & 63;
        int m = m0 + i; int s = m >> 9; int b = m & 511; int t = TT-1-s;
        int base = (b*TT + t)*NLc;
        float v;
        if (k < NLc)        v = obs[base + k] * mask_at(msk, base + k, mode);
        else if (k < 2*NLc) v = mask_at(msk, base + (k - NLc), mode);
        else                v = (t == 0) ? 0.0f : ((float)tp[b*TT+t] - (float)tp[b*TT+t-1]);
        inp[k*64 + i] = v;
    }
    __syncthreads();
    int j = tid;
    float bj = bih[j];
    for (int i = 0; i < 64; i += 4){
        float a0=bj, a1=bj, a2=bj, a3=bj;
        #pragma unroll 13
        for (int k = 0; k < DIN; k++){
            float w = Wsh[k*G3 + j];
            const float4 iv = *(const float4*)(inp + k*64 + i);
            a0 = fmaf(w, iv.x, a0); a1 = fmaf(w, iv.y, a1);
            a2 = fmaf(w, iv.z, a2); a3 = fmaf(w, iv.w, a3);
        }
        g_gix[(m0+i+0)*G3 + j] = a0;
        g_gix[(m0+i+1)*G3 + j] = a1;
        g_gix[(m0+i+2)*G3 + j] = a2;
        g_gix[(m0+i+3)*G3 + j] = a3;
    }
}

// ---- K2: GRU, 4 batch rows/block, Whh resident in smem ----
__global__ void k2_gru(const float* __restrict__ Whh, const float* __restrict__ bhh,
                       const float* __restrict__ Wmu, const float* __restrict__ bmu,
                       const float* __restrict__ Wlv, const float* __restrict__ blv,
                       const float* __restrict__ eps){
    extern __shared__ float sm[];
    float* Wsh = sm;               // 128*384
    float* h4  = sm + HIDc*G3;     // [k][r], 128*4
    float* gh4 = h4 + HIDc*4;      // [j][r], 384*4
    int tid = threadIdx.x;         // 384
    int b0 = blockIdx.x * 4;
    for (int idx = tid; idx < HIDc*G3; idx += G3) Wsh[idx] = Whh[idx];
    for (int idx = tid; idx < HIDc*4; idx += G3) h4[idx] = 0.0f;
    float bj = bhh[tid];
    __syncthreads();
    for (int s = 0; s < TT; s++){
        float a0=bj, a1=bj, a2=bj, a3=bj;
        #pragma unroll 8
        for (int k = 0; k < HIDc; k++){
            float w = Wsh[k*G3 + tid];
            const float4 hv = *(const float4*)(h4 + k*4);
            a0 = fmaf(w, hv.x, a0); a1 = fmaf(w, hv.y, a1);
            a2 = fmaf(w, hv.z, a2); a3 = fmaf(w, hv.w, a3);
        }
        *(float4*)(gh4 + tid*4) = make_float4(a0, a1, a2, a3);
        __syncthreads();
        if (tid < HIDc){
            #pragma unroll
            for (int r = 0; r < 4; r++){
                int base = (s*NB + b0 + r)*G3;
                float gr = g_gix[base + tid];
                float gz = g_gix[base + HIDc + tid];
                float gn = g_gix[base + 2*HIDc + tid];
                float rg = sigmoidf_(gr + gh4[tid*4 + r]);
                float zg = sigmoidf_(gz + gh4[(tid+HIDc)*4 + r]);
                float nn = tanhf(gn + rg*gh4[(tid+2*HIDc)*4 + r]);
                float ho = h4[tid*4 + r];
                h4[tid*4 + r] = (1.0f - zg)*nn + zg*ho;
            }
        }
        __syncthreads();
    }
    if (tid < 256){
        int r = tid >> 6, l = tid & 63;
        int b = b0 + r;
        float mu = bmu[l], lv = blv[l];
        #pragma unroll 8
        for (int k = 0; k < HIDc; k++){
            float hv = h4[k*4 + r];
            mu = fmaf(hv, Wmu[k*LATc + l], mu);
            lv = fmaf(hv, Wlv[k*LATc + l], lv);
        }
        g_z0[b*LATc + l] = mu + eps[b*LATc + l]*expf(0.5f*lv);
        gh4[tid] = 1.0f + lv - mu*mu - expf(lv);
    }
    __syncthreads();
    if (tid < 4){
        float sAcc = 0.f;
        for (int l = 0; l < LATc; l++) sAcc += gh4[tid*64 + l];
        g_klrow[b0 + tid] = sAcc;
    }
}

// ---- K3: RK4 latent ODE, 4 rows/block, MLP weights in smem ----
__device__ __forceinline__ void ode_eval(const float* __restrict__ src, float* __restrict__ ko,
        const float* W1s, const float* W2s, const float* W3s,
        const float* b1s, const float* b2s, const float* b3s,
        float* a1i, float* a2i, int j, int p, int j3, int r3){
    float u0 = b1s[j], u1 = b1s[j];
    #pragma unroll 8
    for (int k = 0; k < LATc; k++){
        float w = W1s[k*HIDc + j];
        const float2 zv = *(const float2*)(src + k*4 + 2*p);
        u0 = fmaf(w, zv.x, u0); u1 = fmaf(w, zv.y, u1);
    }
    a1i[j*4 + 2*p] = tanhf(u0); a1i[j*4 + 2*p + 1] = tanhf(u1);
    __syncthreads();
    float c0 = b2s[j], c1 = b2s[j];
    #pragma unroll 8
    for (int k = 0; k < HIDc; k++){
        float w = W2s[k*HIDc + j];
        const float2 av = *(const float2*)(a1i + k*4 + 2*p);
        c0 = fmaf(w, av.x, c0); c1 = fmaf(w, av.y, c1);
    }
    a2i[j*4 + 2*p] = tanhf(c0); a2i[j*4 + 2*p + 1] = tanhf(c1);
    __syncthreads();
    float o = b3s[j3];
    #pragma unroll 8
    for (int k = 0; k < HIDc; k++)
        o = fmaf(W3s[k*LATc + j3], a2i[k*4 + r3], o);
    ko[j3*4 + r3] = o;
    __syncthreads();
}

__global__ void k3_ode(const float* __restrict__ W1, const float* __restrict__ b1,
                       const float* __restrict__ W2, const float* __restrict__ b2,
                       const float* __restrict__ W3, const float* __restrict__ b3){
    extern __shared__ float sm[];
    float* W1s = sm;
    float* W2s = W1s + LATc*HIDc;
    float* W3s = W2s + HIDc*HIDc;
    float* b1s = W3s + HIDc*LATc;
    float* b2s = b1s + HIDc;
    float* b3s = b2s + HIDc;
    float* yv  = b3s + LATc;
    float* yt  = yv + 256;
    float* ac  = yt + 256;
    float* ko  = ac + 256;
    float* a1i = ko + 256;
    float* a2i = a1i + 512;
    float* gs  = a2i + 512;
    __shared__ int sn;
    int tid = threadIdx.x;                 // 256
    int b0 = blockIdx.x * 4;
    for (int idx = tid; idx < LATc*HIDc; idx += 256) W1s[idx] = W1[idx];
    for (int idx = tid; idx < HIDc*HIDc; idx += 256) W2s[idx] = W2[idx];
    for (int idx = tid; idx < HIDc*LATc; idx += 256) W3s[idx] = W3[idx];
    if (tid < HIDc){ b1s[tid] = b1[tid]; b2s[tid] = b2[tid]; }
    if (tid < LATc) b3s[tid] = b3[tid];
    if (tid < MAXG) gs[tid] = g_grid[tid];
    if (tid == 0) sn = g_niters;
    yv[tid] = g_z0[(b0 + (tid&3))*LATc + (tid>>2)];
    {
        int rr = tid >> 6, ll = tid & 63;
        g_ys[(b0 + rr)*LATc + ll] = g_z0[(b0 + rr)*LATc + ll];
    }
    __syncthreads();
    int n = sn;
    int j  = tid & 127, p  = tid >> 7;
    int j3 = tid & 63,  r3 = tid >> 6;
    for (int i = 0; i < n-1; i++){
        float h = gs[i+1] - gs[i];
        ode_eval(yv, ko, W1s,W2s,W3s,b1s,b2s,b3s,a1i,a2i,j,p,j3,r3);
        ac[tid] = ko[tid];       yt[tid] = yv[tid] + 0.5f*h*ko[tid]; __syncthreads();
        ode_eval(yt, ko, W1s,W2s,W3s,b1s,b2s,b3s,a1i,a2i,j,p,j3,r3);
        ac[tid] += 2.0f*ko[tid]; yt[tid] = yv[tid] + 0.5f*h*ko[tid]; __syncthreads();
        ode_eval(yt, ko, W1s,W2s,W3s,b1s,b2s,b3s,a1i,a2i,j,p,j3,r3);
        ac[tid] += 2.0f*ko[tid]; yt[tid] = yv[tid] + h*ko[tid];      __syncthreads();
        ode_eval(yt, ko, W1s,W2s,W3s,b1s,b2s,b3s,a1i,a2i,j,p,j3,r3);
        yv[tid] = yv[tid] + (h/6.0f)*(ac[tid] + ko[tid]);
        __syncthreads();
        g_ys[((i+1)*NB + b0 + r3)*LATc + j3] = yv[j3*4 + r3];
    }
}

// ---- K4: interpolate z_bt, decode, masked recon partials ----
__global__ void k4_decode(const float* __restrict__ obs, const void* __restrict__ msk,
                          const int* __restrict__ tp,
                          const float* __restrict__ Wo1, const float* __restrict__ bo1,
                          const float* __restrict__ Wo2, const float* __restrict__ bo2,
                          const int* __restrict__ seq_lens){
    extern __shared__ float sm[];
    float* Wo1s = sm;             // 8192
    float* Wo2s = Wo1s + 8192;    // 4096
    float* bo1s = Wo2s + 4096;    // 128
    float* bo2s = bo1s + 128;     // 32
    float* gs   = bo2s + 32;      // 160
    float* zw   = gs + MAXG;      // 8*64
    float* aw   = zw + 512;       // 8*128
    __shared__ float wsum[8]; __shared__ int wcnt[8];
    int tid = threadIdx.x, w = tid>>5, lane = tid&31;
    for (int i = tid; i < 8192; i += 256) Wo1s[i] = Wo1[i];
    for (int i = tid; i < 4096; i += 256) Wo2s[i] = Wo2[i];
    if (tid < 128) bo1s[tid] = bo1[tid];
    if (tid < 32) bo2s[tid] = bo2[tid];
    if (tid < MAXG) gs[tid] = g_grid[tid];
    __syncthreads();
    int n = g_niters;
    int mode = g_mask_mode;
    int pair = blockIdx.x*8 + w;
    int b = pair >> 6, t = pair & 63;
    float q = (float)tp[b*TT+t] / 365.0f;
    int gi = 0;
    for (int i = 1; i <= n-2; i++) if (gs[i] <= q) gi = i;
    float tl = gs[gi], tr = gs[gi+1];
    float den = (tr-tl==0.f)?1.f:(tr-tl);
    float wq = (q-tl)/den;
    const float* y0 = g_ys + (gi*NB + b)*LATc;
    const float* y1 = g_ys + ((gi+1)*NB + b)*LATc;
    float* z = zw + w*64;
    z[lane]    = y0[lane]*(1.f-wq) + y1[lane]*wq;
    z[lane+32] = y0[lane+32]*(1.f-wq) + y1[lane+32]*wq;
    __syncwarp();
    float* a1 = aw + w*128;
    #pragma unroll
    for (int jj = 0; jj < 4; jj++){
        int jx = lane + jj*32;
        float acc = bo1s[jx];
        #pragma unroll 8
        for (int k = 0; k < 64; k++) acc = fmaf(z[k], Wo1s[k*128+jx], acc);
        a1[jx] = fmaxf(acc, 0.f);
    }
    __syncwarp();
    float acc = bo2s[lane];
    #pragma unroll 8
    for (int k = 0; k < 128; k++) acc = fmaf(a1[k], Wo2s[k*32+lane], acc);
    int valid = (t < seq_lens[b]) ? 1 : 0;
    int base = (b*TT+t)*NLc + lane;
    float mval = mask_at(msk, base, mode) * (float)valid;
    float d = acc - obs[base];
    float sq = mval * d * d;
    int cnt = (mval != 0.f) ? 1 : 0;
    for (int o = 16; o > 0; o >>= 1){
        sq  += __shfl_down_sync(0xffffffffu, sq, o);
        cnt += __shfl_down_sync(0xffffffffu, cnt, o);
    }
    if (lane == 0){ wsum[w] = sq; wcnt[w] = cnt; }
    __syncthreads();
    if (tid == 0){
        float s = 0; int c = 0;
        for (int i = 0; i < 8; i++){ s += wsum[i]; c += wcnt[i]; }
        g_rpart[blockIdx.x] = s; g_ncnt[blockIdx.x] = c;
    }
}

// ---- K5: z_eval + survival head ----
__global__ void k5_eval(const int* __restrict__ tp, const int* __restrict__ seq_lens,
                        const float* __restrict__ age,
                        const float* __restrict__ Ws1, const float* __restrict__ bs1,
                        const float* __restrict__ Ws2, const float* __restrict__ bs2,
                        float* __restrict__ out){
    __shared__ float zs[8*66];
    __shared__ float a1s[8*128];
    __shared__ float gsh[MAXG];
    int tid = threadIdx.x, w = tid>>5, lane = tid&31;
    if (tid < MAXG) gsh[tid] = g_grid[tid];
    __syncthreads();
    int n = g_niters;
    int b = blockIdx.x*8 + w;
    int sl = seq_lens[b];
    float q = (float)tp[b*TT + sl - 1] / 365.0f;
    int gi = 0;
    for (int i = 1; i <= n-2; i++) if (gsh[i] <= q) gi = i;
    float tl = gsh[gi], tr = gsh[gi+1];
    float den = (tr-tl==0.f)?1.f:(tr-tl);
    float wq = (q-tl)/den;
    const float* y0 = g_ys + (gi*NB+b)*LATc;
    const float* y1 = g_ys + ((gi+1)*NB+b)*LATc;
    float* z = zs + w*66;
    float za = y0[lane]*(1.f-wq)+y1[lane]*wq;
    float zb = y0[lane+32]*(1.f-wq)+y1[lane+32]*wq;
    z[lane] = za; z[lane+32] = zb;
    out[1026 + b*64 + lane] = za;
    out[1026 + b*64 + lane + 32] = zb;
    if (lane == 0) z[64] = age[b];
    __syncwarp();
    float* a1 = a1s + w*128;
    #pragma unroll
    for (int jj = 0; jj < 4; jj++){
        int jx = lane + jj*32;
        float acc = bs1[jx];
        for (int k = 0; k < 65; k++) acc = fmaf(z[k], Ws1[k*128+jx], acc);
        a1[jx] = fmaxf(acc, 0.f);
    }
    __syncwarp();
    if (lane < 2){
        float acc = bs2[lane];
        for (int k = 0; k < 128; k++) acc = fmaf(a1[k], Ws2[k*2+lane], acc);
        out[b*2 + lane] = acc;
    }
}

// ---- K6: finalize scalars ----
__global__ void k6_final(float* __restrict__ out){
    __shared__ double sd[256]; __shared__ long long si[256]; __shared__ double kd[256];
    int tid = threadIdx.x;
    double s = 0; long long c = 0;
    for (int i = tid; i < 4096; i += 256){ s += (double)g_rpart[i]; c += g_ncnt[i]; }
    double ks = 0;
    for (int i = tid; i < NB; i += 256) ks += (double)g_klrow[i];
    sd[tid]=s; si[tid]=c; kd[tid]=ks; __syncthreads();
    for (int o=128;o>0;o>>=1){ if(tid<o){ sd[tid]+=sd[tid+o]; si[tid]+=si[tid+o]; kd[tid]+=kd[tid+o]; } __syncthreads(); }
    if (tid==0){
        double nn = (double)si[0];
        out[1024] = (nn > 0.0) ? (float)(sd[0] / (nn > 1.0 ? nn : 1.0)) : 0.f;
        out[1025] = (float)(-0.5 * (kd[0] / (double)NB));
    }
}

extern "C" void kernel_launch(void* const* d_in, const int* in_sizes, int n_in,
                              void* d_out, int out_size) {
    const float* obs = (const float*)d_in[0];
    const float* age = (const float*)d_in[1];
    const float* eps = (const float*)d_in[2];
    const float* Wih = (const float*)d_in[3];
    const float* Whh = (const float*)d_in[4];
    const float* bih = (const float*)d_in[5];
    const float* bhh = (const float*)d_in[6];
    const float* Wmu = (const float*)d_in[7];
    const float* bmu = (const float*)d_in[8];
    const float* Wlv = (const float*)d_in[9];
    const float* blv = (const float*)d_in[10];
    const float* W1  = (const float*)d_in[11];
    const float* b1  = (const float*)d_in[12];
    const float* W2  = (const float*)d_in[13];
    const float* b2  = (const float*)d_in[14];
    const float* W3  = (const float*)d_in[15];
    const float* b3  = (const float*)d_in[16];
    const float* Wo1 = (const float*)d_in[17];
    const float* bo1 = (const float*)d_in[18];
    const float* Wo2 = (const float*)d_in[19];
    const float* bo2 = (const float*)d_in[20];
    const float* Ws1 = (const float*)d_in[21];
    const float* bs1 = (const float*)d_in[22];
    const float* Ws2 = (const float*)d_in[23];
    const float* bs2 = (const float*)d_in[24];
    const void*  msk = d_in[25];
    const int*   tp  = (const int*)d_in[26];
    const int*   sq  = (const int*)d_in[27];
    float* out = (float*)d_out;

    cudaFuncSetAttribute(k1_ingemm, cudaFuncAttributeMaxDynamicSharedMemorySize, 116480);
    cudaFuncSetAttribute(k2_gru,    cudaFuncAttributeMaxDynamicSharedMemorySize, 204800);
    cudaFuncSetAttribute(k3_ode,    cudaFuncAttributeMaxDynamicSharedMemorySize, 141184);
    cudaFuncSetAttribute(k4_decode, cudaFuncAttributeMaxDynamicSharedMemorySize, 56576);

    k0_grid<<<1, 512>>>(tp, msk);
    k1_ingemm<<<512, 384, 116480>>>(obs, msk, tp, Wih, bih);
    k2_gru<<<128, 384, 204800>>>(Whh, bhh, Wmu, bmu, Wlv, blv, eps);
    k3_ode<<<128, 256, 141184>>>(W1, b1, W2, b2, W3, b3);
    k4_decode<<<4096, 256, 56576>>>(obs, msk, tp, Wo1, bo1, Wo2, bo2, sq);
    k5_eval<<<64, 256>>>(tp, sq, age, Ws1, bs1, Ws2, bs2, out);
    k6_final<<<1, 256>>>(out);
}

// round 4
// speedup vs baseline: 1.8174x; 1.8174x over previous
#include <cuda_runtime.h>
#include <math.h>

#define NB   512
#define TT   64
#define NLc  32
#define LATc 64
#define HIDc 128
#define G3   384
#define DIN  65
#define MAXG 160

__device__ float g_gix[TT*NB*G3];
__device__ float g_z0 [NB*LATc];
__device__ float g_ys [MAXG*NB*LATc];
__device__ float g_grid[MAXG];
__device__ int   g_niters;
__device__ int   g_mask_mode;
__device__ float g_klrow[NB];
__device__ float g_rpart[4096];
__device__ int   g_ncnt[4096];

__device__ __forceinline__ float sigmoidf_(float x){ return 1.0f/(1.0f+expf(-x)); }
__device__ __forceinline__ float mask_at(const void* m, int idx, int mode){
    if (mode==0) return (float)((const unsigned char*)m)[idx];
    if (mode==1) return (float)((const int*)m)[idx];
    return ((const float*)m)[idx];
}

// packed f32x2 helpers (sm_100+)
__device__ __forceinline__ void ffma2(unsigned long long &acc, unsigned long long a, unsigned long long b){
    asm("fma.rn.f32x2 %0, %1, %2, %0;" : "+l"(acc) : "l"(a), "l"(b));
}
__device__ __forceinline__ unsigned long long dup2(float x){
    unsigned long long r; asm("mov.b64 %0, {%1, %1};" : "=l"(r) : "f"(x)); return r;
}

// ---- K0: grid construction (float64, numpy-matching) + mask dtype detect ----
__global__ void k0_grid(const int* __restrict__ tp, const void* __restrict__ msk){
    __shared__ int smn[NB], smx[NB];
    int b = threadIdx.x;
    smn[b] = tp[b*TT];
    smx[b] = tp[b*TT + TT-1];
    __syncthreads();
    if (b == 0){
        int mn = smn[0], mx = smx[0];
        for (int i = 1; i < NB; i++){ mn = min(mn, smn[i]); mx = max(mx, smx[i]); }
        float q0 = (float)mn / 365.0f, q1 = (float)mx / 365.0f;
        double t0 = (double)q0, t1 = (double)q1;
        int n = (int)ceil((t1 - t0)/0.05 + 1.0);
        if (n < 2) n = 2;
        if (n > MAXG) n = MAXG;
        for (int i = 0; i < n; i++){
            double g = (double)i*0.05 + t0;
            if (i == n-1 && g > t1) g = t1;
            g_grid[i] = (float)g;
        }
        g_niters = n;
    }
    if (b == 1){
        const unsigned int* mw = (const unsigned int*)msk;
        bool alli = true, allf = true;
        for (int i = 0; i < 64; i++){
            unsigned v = mw[i];
            if (v != 0u && v != 1u) alli = false;
            if (v != 0u && v != 0x3f800000u) allf = false;
        }
        g_mask_mode = alli ? 1 : (allf ? 2 : 0);
    }
}

// ---- K1: gix[s][b][:] = inp(b, 63-s) @ Wih + bih ----
__global__ void k1_ingemm(const float* __restrict__ obs, const void* __restrict__ msk,
                          const int* __restrict__ tp, const float* __restrict__ Wih,
                          const float* __restrict__ bih){
    extern __shared__ float sm[];
    float* Wsh = sm;              // 65*384
    float* inp = sm + DIN*G3;     // [k][i], 65*64
    int tid = threadIdx.x;        // 384
    int mode = g_mask_mode;
    for (int idx = tid; idx < DIN*G3; idx += G3) Wsh[idx] = Wih[idx];
    int m0 = blockIdx.x * 64;
    for (int idx = tid; idx < DIN*64; idx += G3){
        int k = idx >> 6, i = idx & 63;
        int m = m0 + i; int s = m >> 9; int b = m & 511; int t = TT-1-s;
        int base = (b*TT + t)*NLc;
        float v;
        if (k < NLc)        v = obs[base + k] * mask_at(msk, base + k, mode);
        else if (k < 2*NLc) v = mask_at(msk, base + (k - NLc), mode);
        else                v = (t == 0) ? 0.0f : ((float)tp[b*TT+t] - (float)tp[b*TT+t-1]);
        inp[k*64 + i] = v;
    }
    __syncthreads();
    int j = tid;
    float bj = bih[j];
    for (int i = 0; i < 64; i += 4){
        float a0=bj, a1=bj, a2=bj, a3=bj;
        #pragma unroll 13
        for (int k = 0; k < DIN; k++){
            float w = Wsh[k*G3 + j];
            const float4 iv = *(const float4*)(inp + k*64 + i);
            a0 = fmaf(w, iv.x, a0); a1 = fmaf(w, iv.y, a1);
            a2 = fmaf(w, iv.z, a2); a3 = fmaf(w, iv.w, a3);
        }
        g_gix[(m0+i+0)*G3 + j] = a0;
        g_gix[(m0+i+1)*G3 + j] = a1;
        g_gix[(m0+i+2)*G3 + j] = a2;
        g_gix[(m0+i+3)*G3 + j] = a3;
    }
}

// ---- K2: GRU, 4 batch rows/block, transposed Whh in smem, float4 loads ----
__device__ __forceinline__ void gru_gate(int e, int s, int b0, float* h4, const float* gh4){
    int j = e >> 2, r = e & 3;
    int base = (s*NB + b0 + r)*G3;
    float gr = g_gix[base + j];
    float gz = g_gix[base + HIDc + j];
    float gn = g_gix[base + 2*HIDc + j];
    float rg = sigmoidf_(gr + gh4[j*4 + r]);
    float zg = sigmoidf_(gz + gh4[(j+HIDc)*4 + r]);
    float nn = tanhf(gn + rg*gh4[(j+2*HIDc)*4 + r]);
    h4[e] = (1.0f - zg)*nn + zg*h4[e];
}

__global__ void __launch_bounds__(384,1) k2_gru(
                       const float* __restrict__ Whh, const float* __restrict__ bhh,
                       const float* __restrict__ Wmu, const float* __restrict__ bmu,
                       const float* __restrict__ Wlv, const float* __restrict__ blv,
                       const float* __restrict__ eps){
    extern __shared__ float sm[];
    float* Wt  = sm;               // 384*132 (transposed, padded)
    float* h4  = sm + 384*132;     // [k][r], 128*4
    float* gh4 = h4 + 512;         // [j][r], 384*4
    int tid = threadIdx.x;         // 384
    int b0 = blockIdx.x * 4;
    // transpose: Wt[j*132 + k] = Whh[k*384 + j]
    for (int k = 0; k < HIDc; k++) Wt[tid*132 + k] = Whh[k*G3 + tid];
    for (int idx = tid; idx < 512; idx += G3) h4[idx] = 0.0f;   // FIX: full coverage
    float bj = bhh[tid];
    const float* wp = Wt + tid*132;
    __syncthreads();
    for (int s = 0; s < TT; s++){
        float a0=bj, a1=bj, a2=bj, a3=bj;
        #pragma unroll 8
        for (int k = 0; k < HIDc; k += 4){
            float4 wv = *(const float4*)(wp + k);
            float4 h0 = *(const float4*)(h4 + k*4);
            float4 h1 = *(const float4*)(h4 + k*4 + 4);
            float4 h2 = *(const float4*)(h4 + k*4 + 8);
            float4 h3 = *(const float4*)(h4 + k*4 + 12);
            a0 = fmaf(wv.x,h0.x,a0); a1 = fmaf(wv.x,h0.y,a1); a2 = fmaf(wv.x,h0.z,a2); a3 = fmaf(wv.x,h0.w,a3);
            a0 = fmaf(wv.y,h1.x,a0); a1 = fmaf(wv.y,h1.y,a1); a2 = fmaf(wv.y,h1.z,a2); a3 = fmaf(wv.y,h1.w,a3);
            a0 = fmaf(wv.z,h2.x,a0); a1 = fmaf(wv.z,h2.y,a1); a2 = fmaf(wv.z,h2.z,a2); a3 = fmaf(wv.z,h2.w,a3);
            a0 = fmaf(wv.w,h3.x,a0); a1 = fmaf(wv.w,h3.y,a1); a2 = fmaf(wv.w,h3.z,a2); a3 = fmaf(wv.w,h3.w,a3);
        }
        *(float4*)(gh4 + tid*4) = make_float4(a0,a1,a2,a3);
        __syncthreads();
        gru_gate(tid, s, b0, h4, gh4);
        if (tid < 128) gru_gate(384+tid, s, b0, h4, gh4);
        __syncthreads();
    }
    if (tid < 256){
        int r = tid >> 6, l = tid & 63;
        int b = b0 + r;
        float mu = bmu[l], lv = blv[l];
        #pragma unroll 8
        for (int k = 0; k < HIDc; k++){
            float hv = h4[k*4 + r];
            mu = fmaf(hv, Wmu[k*LATc + l], mu);
            lv = fmaf(hv, Wlv[k*LATc + l], lv);
        }
        g_z0[b*LATc + l] = mu + eps[b*LATc + l]*expf(0.5f*lv);
        gh4[tid] = 1.0f + lv - mu*mu - expf(lv);
    }
    __syncthreads();
    if (tid < 4){
        float sAcc = 0.f;
        for (int l = 0; l < LATc; l++) sAcc += gh4[tid*64 + l];
        g_klrow[b0 + tid] = sAcc;
    }
}

// ---- K3: RK4 latent ODE, split-K, transposed weights, packed f32x2 FMA ----
__device__ __forceinline__ void mv_stage(const float* __restrict__ wp, const float* __restrict__ zp,
                                         int kn, unsigned long long &a01, unsigned long long &a23){
    #pragma unroll 8
    for (int kk = 0; kk < kn; kk += 4){
        float4 wv = *(const float4*)(wp + kk);
        ulonglong2 z0 = *(const ulonglong2*)(zp + kk*4);
        ulonglong2 z1 = *(const ulonglong2*)(zp + kk*4 + 4);
        ulonglong2 z2 = *(const ulonglong2*)(zp + kk*4 + 8);
        ulonglong2 z3 = *(const ulonglong2*)(zp + kk*4 + 12);
        unsigned long long w;
        w = dup2(wv.x); ffma2(a01, w, z0.x); ffma2(a23, w, z0.y);
        w = dup2(wv.y); ffma2(a01, w, z1.x); ffma2(a23, w, z1.y);
        w = dup2(wv.z); ffma2(a01, w, z2.x); ffma2(a23, w, z2.y);
        w = dup2(wv.w); ffma2(a01, w, z3.x); ffma2(a23, w, z3.y);
    }
}

__device__ __forceinline__ void ode_eval2(const float* __restrict__ src, float* __restrict__ ko,
        const float* W1t, const float* W2t, const float* W3t,
        const float* b1s, const float* b2s, const float* b3s,
        float* a1i, float* a2i, float* pbuf,
        int tid, int j, int p, int j3, int q){
    // stage1: out 128, K=64 split in halves of 32
    {
        unsigned long long a01=0ull, a23=0ull;
        mv_stage(W1t + j*68 + p*32, src + p*128, 32, a01, a23);
        ulonglong2 v; v.x=a01; v.y=a23;
        *(ulonglong2*)(pbuf + (p*128 + j)*4) = v;
    }
    __syncthreads();
    {
        float s0 = pbuf[tid] + pbuf[512+tid] + b1s[tid>>2];
        float s1 = pbuf[256+tid] + pbuf[768+tid] + b1s[(256+tid)>>2];
        a1i[tid] = tanhf(s0); a1i[256+tid] = tanhf(s1);
    }
    __syncthreads();
    // stage2: out 128, K=128 split in halves of 64
    {
        unsigned long long a01=0ull, a23=0ull;
        mv_stage(W2t + j*132 + p*64, a1i + p*256, 64, a01, a23);
        ulonglong2 v; v.x=a01; v.y=a23;
        *(ulonglong2*)(pbuf + (p*128 + j)*4) = v;
    }
    __syncthreads();
    {
        float s0 = pbuf[tid] + pbuf[512+tid] + b2s[tid>>2];
        float s1 = pbuf[256+tid] + pbuf[768+tid] + b2s[(256+tid)>>2];
        a2i[tid] = tanhf(s0); a2i[256+tid] = tanhf(s1);
    }
    __syncthreads();
    // stage3: out 64, K=128 split in quarters of 32
    {
        unsigned long long a01=0ull, a23=0ull;
        mv_stage(W3t + j3*132 + q*32, a2i + q*128, 32, a01, a23);
        ulonglong2 v; v.x=a01; v.y=a23;
        *(ulonglong2*)(pbuf + (q*64 + j3)*4) = v;
    }
    __syncthreads();
    ko[tid] = pbuf[tid] + pbuf[256+tid] + pbuf[512+tid] + pbuf[768+tid] + b3s[tid>>2];
    __syncthreads();
}

__global__ void __launch_bounds__(256,1) k3_ode(
                       const float* __restrict__ W1, const float* __restrict__ b1,
                       const float* __restrict__ W2, const float* __restrict__ b2,
                       const float* __restrict__ W3, const float* __restrict__ b3){
    extern __shared__ float sm[];
    float* W1t = sm;                       // 128*68
    float* W2t = W1t + 128*68;             // 128*132
    float* W3t = W2t + 128*132;            // 64*132
    float* b1s = W3t + 64*132;             // 128
    float* b2s = b1s + 128;                // 128
    float* b3s = b2s + 128;                // 64
    float* yv  = b3s + 64;                 // 256
    float* yt  = yv + 256;
    float* ac  = yt + 256;
    float* ko  = ac + 256;
    float* a1i = ko + 256;                 // 512
    float* a2i = a1i + 512;                // 512
    float* pbuf= a2i + 512;                // 1024
    float* gs  = pbuf + 1024;              // MAXG
    __shared__ int sn;
    int tid = threadIdx.x;                 // 256
    int b0 = blockIdx.x * 4;
    for (int idx = tid; idx < 8192; idx += 256){ int k=idx>>7, j=idx&127; W1t[j*68+k]  = W1[idx]; }
    for (int idx = tid; idx < 16384; idx += 256){ int k=idx>>7, j=idx&127; W2t[j*132+k] = W2[idx]; }
    for (int idx = tid; idx < 8192; idx += 256){ int k=idx>>6, j=idx&63;  W3t[j*132+k] = W3[idx]; }
    if (tid < HIDc){ b1s[tid] = b1[tid]; b2s[tid] = b2[tid]; }
    if (tid < LATc) b3s[tid] = b3[tid];
    if (tid < MAXG) gs[tid] = g_grid[tid];
    if (tid == 0) sn = g_niters;
    yv[tid] = g_z0[(b0 + (tid&3))*LATc + (tid>>2)];
    {
        int rr = tid >> 6, ll = tid & 63;
        g_ys[(b0 + rr)*LATc + ll] = g_z0[(b0 + rr)*LATc + ll];
    }
    __syncthreads();
    int n = sn;
    int j  = tid & 127, p  = tid >> 7;
    int j3 = tid & 63,  q  = tid >> 6;
    for (int i = 0; i < n-1; i++){
        float h = gs[i+1] - gs[i];
        ode_eval2(yv, ko, W1t,W2t,W3t,b1s,b2s,b3s,a1i,a2i,pbuf,tid,j,p,j3,q);
        ac[tid] = ko[tid];       yt[tid] = yv[tid] + 0.5f*h*ko[tid]; __syncthreads();
        ode_eval2(yt, ko, W1t,W2t,W3t,b1s,b2s,b3s,a1i,a2i,pbuf,tid,j,p,j3,q);
        ac[tid] += 2.0f*ko[tid]; yt[tid] = yv[tid] + 0.5f*h*ko[tid]; __syncthreads();
        ode_eval2(yt, ko, W1t,W2t,W3t,b1s,b2s,b3s,a1i,a2i,pbuf,tid,j,p,j3,q);
        ac[tid] += 2.0f*ko[tid]; yt[tid] = yv[tid] + h*ko[tid];      __syncthreads();
        ode_eval2(yt, ko, W1t,W2t,W3t,b1s,b2s,b3s,a1i,a2i,pbuf,tid,j,p,j3,q);
        yv[tid] = yv[tid] + (h/6.0f)*(ac[tid] + ko[tid]);
        __syncthreads();
        g_ys[((i+1)*NB + b0 + q)*LATc + j3] = yv[j3*4 + q];
    }
}

// ---- K4: interpolate z_bt, decode, masked recon partials ----
__global__ void k4_decode(const float* __restrict__ obs, const void* __restrict__ msk,
                          const int* __restrict__ tp,
                          const float* __restrict__ Wo1, const float* __restrict__ bo1,
                          const float* __restrict__ Wo2, const float* __restrict__ bo2,
                          const int* __restrict__ seq_lens){
    extern __shared__ float sm[];
    float* Wo1s = sm;             // 8192
    float* Wo2s = Wo1s + 8192;    // 4096
    float* bo1s = Wo2s + 4096;    // 128
    float* bo2s = bo1s + 128;     // 32
    float* gs   = bo2s + 32;      // 160
    float* zw   = gs + MAXG;      // 8*64
    float* aw   = zw + 512;       // 8*128
    __shared__ float wsum[8]; __shared__ int wcnt[8];
    int tid = threadIdx.x, w = tid>>5, lane = tid&31;
    for (int i = tid; i < 8192; i += 256) Wo1s[i] = Wo1[i];
    for (int i = tid; i < 4096; i += 256) Wo2s[i] = Wo2[i];
    if (tid < 128) bo1s[tid] = bo1[tid];
    if (tid < 32) bo2s[tid] = bo2[tid];
    if (tid < MAXG) gs[tid] = g_grid[tid];
    __syncthreads();
    int n = g_niters;
    int mode = g_mask_mode;
    int pair = blockIdx.x*8 + w;
    int b = pair >> 6, t = pair & 63;
    float q = (float)tp[b*TT+t] / 365.0f;
    int gi = 0;
    for (int i = 1; i <= n-2; i++) if (gs[i] <= q) gi = i;
    float tl = gs[gi], tr = gs[gi+1];
    float den = (tr-tl==0.f)?1.f:(tr-tl);
    float wq = (q-tl)/den;
    const float* y0 = g_ys + (gi*NB + b)*LATc;
    const float* y1 = g_ys + ((gi+1)*NB + b)*LATc;
    float* z = zw + w*64;
    z[lane]    = y0[lane]*(1.f-wq) + y1[lane]*wq;
    z[lane+32] = y0[lane+32]*(1.f-wq) + y1[lane+32]*wq;
    __syncwarp();
    float* a1 = aw + w*128;
    #pragma unroll
    for (int jj = 0; jj < 4; jj++){
        int jx = lane + jj*32;
        float acc = bo1s[jx];
        #pragma unroll 8
        for (int k = 0; k < 64; k++) acc = fmaf(z[k], Wo1s[k*128+jx], acc);
        a1[jx] = fmaxf(acc, 0.f);
    }
    __syncwarp();
    float acc = bo2s[lane];
    #pragma unroll 8
    for (int k = 0; k < 128; k++) acc = fmaf(a1[k], Wo2s[k*32+lane], acc);
    int valid = (t < seq_lens[b]) ? 1 : 0;
    int base = (b*TT+t)*NLc + lane;
    float mval = mask_at(msk, base, mode) * (float)valid;
    float d = acc - obs[base];
    float sq = mval * d * d;
    int cnt = (mval != 0.f) ? 1 : 0;
    for (int o = 16; o > 0; o >>= 1){
        sq  += __shfl_down_sync(0xffffffffu, sq, o);
        cnt += __shfl_down_sync(0xffffffffu, cnt, o);
    }
    if (lane == 0){ wsum[w] = sq; wcnt[w] = cnt; }
    __syncthreads();
    if (tid == 0){
        float s = 0; int c = 0;
        for (int i = 0; i < 8; i++){ s += wsum[i]; c += wcnt[i]; }
        g_rpart[blockIdx.x] = s; g_ncnt[blockIdx.x] = c;
    }
}

// ---- K5: z_eval + survival head ----
__global__ void k5_eval(const int* __restrict__ tp, const int* __restrict__ seq_lens,
                        const float* __restrict__ age,
                        const float* __restrict__ Ws1, const float* __restrict__ bs1,
                        const float* __restrict__ Ws2, const float* __restrict__ bs2,
                        float* __restrict__ out){
    __shared__ float zs[8*66];
    __shared__ float a1s[8*128];
    __shared__ float gsh[MAXG];
    int tid = threadIdx.x, w = tid>>5, lane = tid&31;
    if (tid < MAXG) gsh[tid] = g_grid[tid];
    __syncthreads();
    int n = g_niters;
    int b = blockIdx.x*8 + w;
    int sl = seq_lens[b];
    float q = (float)tp[b*TT + sl - 1] / 365.0f;
    int gi = 0;
    for (int i = 1; i <= n-2; i++) if (gsh[i] <= q) gi = i;
    float tl = gsh[gi], tr = gsh[gi+1];
    float den = (tr-tl==0.f)?1.f:(tr-tl);
    float wq = (q-tl)/den;
    const float* y0 = g_ys + (gi*NB+b)*LATc;
    const float* y1 = g_ys + ((gi+1)*NB+b)*LATc;
    float* z = zs + w*66;
    float za = y0[lane]*(1.f-wq)+y1[lane]*wq;
    float zb = y0[lane+32]*(1.f-wq)+y1[lane+32]*wq;
    z[lane] = za; z[lane+32] = zb;
    out[1026 + b*64 + lane] = za;
    out[1026 + b*64 + lane + 32] = zb;
    if (lane == 0) z[64] = age[b];
    __syncwarp();
    float* a1 = a1s + w*128;
    #pragma unroll
    for (int jj = 0; jj < 4; jj++){
        int jx = lane + jj*32;
        float acc = bs1[jx];
        for (int k = 0; k < 65; k++) acc = fmaf(z[k], Ws1[k*128+jx], acc);
        a1[jx] = fmaxf(acc, 0.f);
    }
    __syncwarp();
    if (lane < 2){
        float acc = bs2[lane];
        for (int k = 0; k < 128; k++) acc = fmaf(a1[k], Ws2[k*2+lane], acc);
        out[b*2 + lane] = acc;
    }
}

// ---- K6: finalize scalars ----
__global__ void k6_final(float* __restrict__ out){
    __shared__ double sd[256]; __shared__ long long si[256]; __shared__ double kd[256];
    int tid = threadIdx.x;
    double s = 0; long long c = 0;
    for (int i = tid; i < 4096; i += 256){ s += (double)g_rpart[i]; c += g_ncnt[i]; }
    double ks = 0;
    for (int i = tid; i < NB; i += 256) ks += (double)g_klrow[i];
    sd[tid]=s; si[tid]=c; kd[tid]=ks; __syncthreads();
    for (int o=128;o>0;o>>=1){ if(tid<o){ sd[tid]+=sd[tid+o]; si[tid]+=si[tid+o]; kd[tid]+=kd[tid+o]; } __syncthreads(); }
    if (tid==0){
        double nn = (double)si[0];
        out[1024] = (nn > 0.0) ? (float)(sd[0] / (nn > 1.0 ? nn : 1.0)) : 0.f;
        out[1025] = (float)(-0.5 * (kd[0] / (double)NB));
    }
}

extern "C" void kernel_launch(void* const* d_in, const int* in_sizes, int n_in,
                              void* d_out, int out_size) {
    const float* obs = (const float*)d_in[0];
    const float* age = (const float*)d_in[1];
    const float* eps = (const float*)d_in[2];
    const float* Wih = (const float*)d_in[3];
    const float* Whh = (const float*)d_in[4];
    const float* bih = (const float*)d_in[5];
    const float* bhh = (const float*)d_in[6];
    const float* Wmu = (const float*)d_in[7];
    const float* bmu = (const float*)d_in[8];
    const float* Wlv = (const float*)d_in[9];
    const float* blv = (const float*)d_in[10];
    const float* W1  = (const float*)d_in[11];
    const float* b1  = (const float*)d_in[12];
    const float* W2  = (const float*)d_in[13];
    const float* b2  = (const float*)d_in[14];
    const float* W3  = (const float*)d_in[15];
    const float* b3  = (const float*)d_in[16];
    const float* Wo1 = (const float*)d_in[17];
    const float* bo1 = (const float*)d_in[18];
    const float* Wo2 = (const float*)d_in[19];
    const float* bo2 = (const float*)d_in[20];
    const float* Ws1 = (const float*)d_in[21];
    const float* bs1 = (const float*)d_in[22];
    const float* Ws2 = (const float*)d_in[23];
    const float* bs2 = (const float*)d_in[24];
    const void*  msk = d_in[25];
    const int*   tp  = (const int*)d_in[26];
    const int*   sq  = (const int*)d_in[27];
    float* out = (float*)d_out;

    cudaFuncSetAttribute(k1_ingemm, cudaFuncAttributeMaxDynamicSharedMemorySize, 116480);
    cudaFuncSetAttribute(k2_gru,    cudaFuncAttributeMaxDynamicSharedMemorySize, 210944);
    cudaFuncSetAttribute(k3_ode,    cudaFuncAttributeMaxDynamicSharedMemorySize, 150656);
    cudaFuncSetAttribute(k4_decode, cudaFuncAttributeMaxDynamicSharedMemorySize, 56576);

    k0_grid<<<1, 512>>>(tp, msk);
    k1_ingemm<<<512, 384, 116480>>>(obs, msk, tp, Wih, bih);
    k2_gru<<<128, 384, 210944>>>(Whh, bhh, Wmu, bmu, Wlv, blv, eps);
    k3_ode<<<128, 256, 150656>>>(W1, b1, W2, b2, W3, b3);
    k4_decode<<<4096, 256, 56576>>>(obs, msk, tp, Wo1, bo1, Wo2, bo2, sq);
    k5_eval<<<64, 256>>>(tp, sq, age, Ws1, bs1, Ws2, bs2, out);
    k6_final<<<1, 256>>>(out);
}

// round 5
// speedup vs baseline: 2.2551x; 1.2408x over previous
#include <cuda_runtime.h>
#include <math.h>

#define NB   512
#define TT   64
#define NLc  32
#define LATc 64
#define HIDc 128
#define G3   384
#define DIN  65
#define MAXG 160

__device__ float g_gix[TT*NB*G3];
__device__ float g_z0 [NB*LATc];
__device__ float g_ys [MAXG*NB*LATc];
__device__ float g_grid[MAXG];
__device__ int   g_niters;
__device__ int   g_mask_mode;
__device__ float g_klrow[NB];
__device__ float g_rpart[4096];
__device__ int   g_ncnt[4096];

__device__ __forceinline__ float sigmoidf_(float x){ return 1.0f/(1.0f+expf(-x)); }
__device__ __forceinline__ float mask_at(const void* m, int idx, int mode){
    if (mode==0) return (float)((const unsigned char*)m)[idx];
    if (mode==1) return (float)((const int*)m)[idx];
    return ((const float*)m)[idx];
}

// packed f32x2 helpers (sm_100+)
__device__ __forceinline__ void ffma2(unsigned long long &acc, unsigned long long a, unsigned long long b){
    asm("fma.rn.f32x2 %0, %1, %2, %0;" : "+l"(acc) : "l"(a), "l"(b));
}
__device__ __forceinline__ unsigned long long dup2(float x){
    unsigned long long r; asm("mov.b64 %0, {%1, %1};" : "=l"(r) : "f"(x)); return r;
}
__device__ __forceinline__ float tanh_fast(float x){
    float y; asm("tanh.approx.f32 %0, %1;" : "=f"(y) : "f"(x)); return y;
}

// ---- K0: grid construction (float64, numpy-matching) + mask dtype detect ----
__global__ void k0_grid(const int* __restrict__ tp, const void* __restrict__ msk){
    __shared__ int smn[NB], smx[NB];
    int b = threadIdx.x;
    smn[b] = tp[b*TT];
    smx[b] = tp[b*TT + TT-1];
    __syncthreads();
    if (b == 0){
        int mn = smn[0], mx = smx[0];
        for (int i = 1; i < NB; i++){ mn = min(mn, smn[i]); mx = max(mx, smx[i]); }
        float q0 = (float)mn / 365.0f, q1 = (float)mx / 365.0f;
        double t0 = (double)q0, t1 = (double)q1;
        int n = (int)ceil((t1 - t0)/0.05 + 1.0);
        if (n < 2) n = 2;
        if (n > MAXG) n = MAXG;
        for (int i = 0; i < n; i++){
            double g = (double)i*0.05 + t0;
            if (i == n-1 && g > t1) g = t1;
            g_grid[i] = (float)g;
        }
        g_niters = n;
    }
    if (b == 1){
        const unsigned int* mw = (const unsigned int*)msk;
        bool alli = true, allf = true;
        for (int i = 0; i < 64; i++){
            unsigned v = mw[i];
            if (v != 0u && v != 1u) alli = false;
            if (v != 0u && v != 0x3f800000u) allf = false;
        }
        g_mask_mode = alli ? 1 : (allf ? 2 : 0);
    }
}

// ---- K1: gix[s][b][:] = inp(b, 63-s) @ Wih + bih ----
__global__ void k1_ingemm(const float* __restrict__ obs, const void* __restrict__ msk,
                          const int* __restrict__ tp, const float* __restrict__ Wih,
                          const float* __restrict__ bih){
    extern __shared__ float sm[];
    float* Wsh = sm;              // 65*384
    float* inp = sm + DIN*G3;     // [k][i], 65*64
    int tid = threadIdx.x;        // 384
    int mode = g_mask_mode;
    for (int idx = tid; idx < DIN*G3; idx += G3) Wsh[idx] = Wih[idx];
    int m0 = blockIdx.x * 64;
    for (int idx = tid; idx < DIN*64; idx += G3){
        int k = idx >> 6, i = idx & 63;
        int m = m0 + i; int s = m >> 9; int b = m & 511; int t = TT-1-s;
        int base = (b*TT + t)*NLc;
        float v;
        if (k < NLc)        v = obs[base + k] * mask_at(msk, base + k, mode);
        else if (k < 2*NLc) v = mask_at(msk, base + (k - NLc), mode);
        else                v = (t == 0) ? 0.0f : ((float)tp[b*TT+t] - (float)tp[b*TT+t-1]);
        inp[k*64 + i] = v;
    }
    __syncthreads();
    int j = tid;
    float bj = bih[j];
    for (int i = 0; i < 64; i += 4){
        float a0=bj, a1=bj, a2=bj, a3=bj;
        #pragma unroll 13
        for (int k = 0; k < DIN; k++){
            float w = Wsh[k*G3 + j];
            const float4 iv = *(const float4*)(inp + k*64 + i);
            a0 = fmaf(w, iv.x, a0); a1 = fmaf(w, iv.y, a1);
            a2 = fmaf(w, iv.z, a2); a3 = fmaf(w, iv.w, a3);
        }
        g_gix[(m0+i+0)*G3 + j] = a0;
        g_gix[(m0+i+1)*G3 + j] = a1;
        g_gix[(m0+i+2)*G3 + j] = a2;
        g_gix[(m0+i+3)*G3 + j] = a3;
    }
}

// ---- K2: GRU, 4 batch rows/block, transposed Whh in smem, float4 loads ----
__device__ __forceinline__ void gru_gate(int e, int s, int b0, float* h4, const float* gh4){
    int j = e >> 2, r = e & 3;
    int base = (s*NB + b0 + r)*G3;
    float gr = g_gix[base + j];
    float gz = g_gix[base + HIDc + j];
    float gn = g_gix[base + 2*HIDc + j];
    float rg = sigmoidf_(gr + gh4[j*4 + r]);
    float zg = sigmoidf_(gz + gh4[(j+HIDc)*4 + r]);
    float nn = tanhf(gn + rg*gh4[(j+2*HIDc)*4 + r]);
    h4[e] = (1.0f - zg)*nn + zg*h4[e];
}

__global__ void __launch_bounds__(384,1) k2_gru(
                       const float* __restrict__ Whh, const float* __restrict__ bhh,
                       const float* __restrict__ Wmu, const float* __restrict__ bmu,
                       const float* __restrict__ Wlv, const float* __restrict__ blv,
                       const float* __restrict__ eps){
    extern __shared__ float sm[];
    float* Wt  = sm;               // 384*132 (transposed, padded)
    float* h4  = sm + 384*132;     // [k][r], 128*4
    float* gh4 = h4 + 512;         // [j][r], 384*4
    int tid = threadIdx.x;         // 384
    int b0 = blockIdx.x * 4;
    for (int k = 0; k < HIDc; k++) Wt[tid*132 + k] = Whh[k*G3 + tid];
    for (int idx = tid; idx < 512; idx += G3) h4[idx] = 0.0f;
    float bj = bhh[tid];
    const float* wp = Wt + tid*132;
    __syncthreads();
    for (int s = 0; s < TT; s++){
        float a0=bj, a1=bj, a2=bj, a3=bj;
        #pragma unroll 8
        for (int k = 0; k < HIDc; k += 4){
            float4 wv = *(const float4*)(wp + k);
            float4 h0 = *(const float4*)(h4 + k*4);
            float4 h1 = *(const float4*)(h4 + k*4 + 4);
            float4 h2 = *(const float4*)(h4 + k*4 + 8);
            float4 h3 = *(const float4*)(h4 + k*4 + 12);
            a0 = fmaf(wv.x,h0.x,a0); a1 = fmaf(wv.x,h0.y,a1); a2 = fmaf(wv.x,h0.z,a2); a3 = fmaf(wv.x,h0.w,a3);
            a0 = fmaf(wv.y,h1.x,a0); a1 = fmaf(wv.y,h1.y,a1); a2 = fmaf(wv.y,h1.z,a2); a3 = fmaf(wv.y,h1.w,a3);
            a0 = fmaf(wv.z,h2.x,a0); a1 = fmaf(wv.z,h2.y,a1); a2 = fmaf(wv.z,h2.z,a2); a3 = fmaf(wv.z,h2.w,a3);
            a0 = fmaf(wv.w,h3.x,a0); a1 = fmaf(wv.w,h3.y,a1); a2 = fmaf(wv.w,h3.z,a2); a3 = fmaf(wv.w,h3.w,a3);
        }
        *(float4*)(gh4 + tid*4) = make_float4(a0,a1,a2,a3);
        __syncthreads();
        gru_gate(tid, s, b0, h4, gh4);
        if (tid < 128) gru_gate(384+tid, s, b0, h4, gh4);
        __syncthreads();
    }
    if (tid < 256){
        int r = tid >> 6, l = tid & 63;
        int b = b0 + r;
        float mu = bmu[l], lv = blv[l];
        #pragma unroll 8
        for (int k = 0; k < HIDc; k++){
            float hv = h4[k*4 + r];
            mu = fmaf(hv, Wmu[k*LATc + l], mu);
            lv = fmaf(hv, Wlv[k*LATc + l], lv);
        }
        g_z0[b*LATc + l] = mu + eps[b*LATc + l]*expf(0.5f*lv);
        gh4[tid] = 1.0f + lv - mu*mu - expf(lv);
    }
    __syncthreads();
    if (tid < 4){
        float sAcc = 0.f;
        for (int l = 0; l < LATc; l++) sAcc += gh4[tid*64 + l];
        g_klrow[b0 + tid] = sAcc;
    }
}

// ---- K3: RK4 latent ODE — weights in REGISTERS, broadcast state LDS, f32x2 FMA ----
__device__ __forceinline__ void mv_reg(const float* __restrict__ wr, const float* __restrict__ zp,
                                       int kn, unsigned long long &a01, unsigned long long &a23){
    #pragma unroll
    for (int kk = 0; kk < 64; kk++){
        if (kk >= kn) break;
        ulonglong2 z = *(const ulonglong2*)(zp + kk*4);   // broadcast, warp-uniform
        unsigned long long w = dup2(wr[kk]);
        ffma2(a01, w, z.x); ffma2(a23, w, z.y);
    }
}

__global__ void __launch_bounds__(256,1) k3_ode(
                       const float* __restrict__ W1, const float* __restrict__ b1,
                       const float* __restrict__ W2, const float* __restrict__ b2,
                       const float* __restrict__ W3, const float* __restrict__ b3){
    __shared__ float yv[256], yt[256], ac[256], ko[256];
    __shared__ float a1i[512], a2i[512], pbuf[1024];
    __shared__ float b1s[HIDc], b2s[HIDc], b3s[LATc], gs[MAXG];
    __shared__ int sn;
    int tid = threadIdx.x;                 // 256
    int b0 = blockIdx.x * 4;
    int j  = tid & 127, p  = tid >> 7;
    int j3 = tid & 63,  q  = tid >> 6;

    // per-thread weight slices in registers
    float w1r[32], w2r[64], w3r[32];
    #pragma unroll
    for (int k = 0; k < 32; k++) w1r[k] = W1[(p*32 + k)*HIDc + j];
    #pragma unroll
    for (int k = 0; k < 64; k++) w2r[k] = W2[(p*64 + k)*HIDc + j];
    #pragma unroll
    for (int k = 0; k < 32; k++) w3r[k] = W3[(q*32 + k)*LATc + j3];

    if (tid < HIDc){ b1s[tid] = b1[tid]; b2s[tid] = b2[tid]; }
    if (tid < LATc) b3s[tid] = b3[tid];
    if (tid < MAXG) gs[tid] = g_grid[tid];
    if (tid == 0) sn = g_niters;
    yv[tid] = g_z0[(b0 + (tid&3))*LATc + (tid>>2)];
    {
        int rr = tid >> 6, ll = tid & 63;
        g_ys[(b0 + rr)*LATc + ll] = g_z0[(b0 + rr)*LATc + ll];
    }
    __syncthreads();
    int n = sn;

    for (int i = 0; i < n-1; i++){
        float h = gs[i+1] - gs[i];
        #pragma unroll
        for (int st = 0; st < 4; st++){
            const float* src = (st == 0) ? yv : yt;
            // stage1: out 128, K=64 split in halves of 32
            {
                unsigned long long a01=0ull, a23=0ull;
                mv_reg(w1r, src + p*128, 32, a01, a23);
                ulonglong2 v; v.x=a01; v.y=a23;
                *(ulonglong2*)(pbuf + (p*128 + j)*4) = v;
            }
            __syncthreads();
            {
                float s0 = pbuf[tid] + pbuf[512+tid] + b1s[tid>>2];
                float s1 = pbuf[256+tid] + pbuf[768+tid] + b1s[(256+tid)>>2];
                a1i[tid] = tanh_fast(s0); a1i[256+tid] = tanh_fast(s1);
            }
            __syncthreads();
            // stage2: out 128, K=128 split in halves of 64
            {
                unsigned long long a01=0ull, a23=0ull;
                mv_reg(w2r, a1i + p*256, 64, a01, a23);
                ulonglong2 v; v.x=a01; v.y=a23;
                *(ulonglong2*)(pbuf + (p*128 + j)*4) = v;
            }
            __syncthreads();
            {
                float s0 = pbuf[tid] + pbuf[512+tid] + b2s[tid>>2];
                float s1 = pbuf[256+tid] + pbuf[768+tid] + b2s[(256+tid)>>2];
                a2i[tid] = tanh_fast(s0); a2i[256+tid] = tanh_fast(s1);
            }
            __syncthreads();
            // stage3: out 64, K=128 split in quarters of 32
            {
                unsigned long long a01=0ull, a23=0ull;
                mv_reg(w3r, a2i + q*128, 32, a01, a23);
                ulonglong2 v; v.x=a01; v.y=a23;
                *(ulonglong2*)(pbuf + (q*64 + j3)*4) = v;
            }
            __syncthreads();
            float kv = pbuf[tid] + pbuf[256+tid] + pbuf[512+tid] + pbuf[768+tid] + b3s[tid>>2];
            ko[tid] = kv;
            // RK4 bookkeeping
            if (st == 0){ ac[tid] = kv;        yt[tid] = yv[tid] + 0.5f*h*kv; }
            else if (st == 1){ ac[tid] += 2.0f*kv; yt[tid] = yv[tid] + 0.5f*h*kv; }
            else if (st == 2){ ac[tid] += 2.0f*kv; yt[tid] = yv[tid] + h*kv; }
            else { yv[tid] = yv[tid] + (h/6.0f)*(ac[tid] + kv); }
            __syncthreads();
        }
        g_ys[((i+1)*NB + b0 + q)*LATc + j3] = yv[j3*4 + q];
    }
}

// ---- K4: interpolate z_bt, decode, masked recon partials ----
__global__ void k4_decode(const float* __restrict__ obs, const void* __restrict__ msk,
                          const int* __restrict__ tp,
                          const float* __restrict__ Wo1, const float* __restrict__ bo1,
                          const float* __restrict__ Wo2, const float* __restrict__ bo2,
                          const int* __restrict__ seq_lens){
    extern __shared__ float sm[];
    float* Wo1s = sm;             // 8192
    float* Wo2s = Wo1s + 8192;    // 4096
    float* bo1s = Wo2s + 4096;    // 128
    float* bo2s = bo1s + 128;     // 32
    float* gs   = bo2s + 32;      // 160
    float* zw   = gs + MAXG;      // 8*64
    float* aw   = zw + 512;       // 8*128
    __shared__ float wsum[8]; __shared__ int wcnt[8];
    int tid = threadIdx.x, w = tid>>5, lane = tid&31;
    for (int i = tid; i < 8192; i += 256) Wo1s[i] = Wo1[i];
    for (int i = tid; i < 4096; i += 256) Wo2s[i] = Wo2[i];
    if (tid < 128) bo1s[tid] = bo1[tid];
    if (tid < 32) bo2s[tid] = bo2[tid];
    if (tid < MAXG) gs[tid] = g_grid[tid];
    __syncthreads();
    int n = g_niters;
    int mode = g_mask_mode;
    int pair = blockIdx.x*8 + w;
    int b = pair >> 6, t = pair & 63;
    float q = (float)tp[b*TT+t] / 365.0f;
    int gi = 0;
    for (int i = 1; i <= n-2; i++) if (gs[i] <= q) gi = i;
    float tl = gs[gi], tr = gs[gi+1];
    float den = (tr-tl==0.f)?1.f:(tr-tl);
    float wq = (q-tl)/den;
    const float* y0 = g_ys + (gi*NB + b)*LATc;
    const float* y1 = g_ys + ((gi+1)*NB + b)*LATc;
    float* z = zw + w*64;
    z[lane]    = y0[lane]*(1.f-wq) + y1[lane]*wq;
    z[lane+32] = y0[lane+32]*(1.f-wq) + y1[lane+32]*wq;
    __syncwarp();
    float* a1 = aw + w*128;
    #pragma unroll
    for (int jj = 0; jj < 4; jj++){
        int jx = lane + jj*32;
        float acc = bo1s[jx];
        #pragma unroll 8
        for (int k = 0; k < 64; k++) acc = fmaf(z[k], Wo1s[k*128+jx], acc);
        a1[jx] = fmaxf(acc, 0.f);
    }
    __syncwarp();
    float acc = bo2s[lane];
    #pragma unroll 8
    for (int k = 0; k < 128; k++) acc = fmaf(a1[k], Wo2s[k*32+lane], acc);
    int valid = (t < seq_lens[b]) ? 1 : 0;
    int base = (b*TT+t)*NLc + lane;
    float mval = mask_at(msk, base, mode) * (float)valid;
    float d = acc - obs[base];
    float sq = mval * d * d;
    int cnt = (mval != 0.f) ? 1 : 0;
    for (int o = 16; o > 0; o >>= 1){
        sq  += __shfl_down_sync(0xffffffffu, sq, o);
        cnt += __shfl_down_sync(0xffffffffu, cnt, o);
    }
    if (lane == 0){ wsum[w] = sq; wcnt[w] = cnt; }
    __syncthreads();
    if (tid == 0){
        float s = 0; int c = 0;
        for (int i = 0; i < 8; i++){ s += wsum[i]; c += wcnt[i]; }
        g_rpart[blockIdx.x] = s; g_ncnt[blockIdx.x] = c;
    }
}

// ---- K5: z_eval + survival head ----
__global__ void k5_eval(const int* __restrict__ tp, const int* __restrict__ seq_lens,
                        const float* __restrict__ age,
                        const float* __restrict__ Ws1, const float* __restrict__ bs1,
                        const float* __restrict__ Ws2, const float* __restrict__ bs2,
                        float* __restrict__ out){
    __shared__ float zs[8*66];
    __shared__ float a1s[8*128];
    __shared__ float gsh[MAXG];
    int tid = threadIdx.x, w = tid>>5, lane = tid&31;
    if (tid < MAXG) gsh[tid] = g_grid[tid];
    __syncthreads();
    int n = g_niters;
    int b = blockIdx.x*8 + w;
    int sl = seq_lens[b];
    float q = (float)tp[b*TT + sl - 1] / 365.0f;
    int gi = 0;
    for (int i = 1; i <= n-2; i++) if (gsh[i] <= q) gi = i;
    float tl = gsh[gi], tr = gsh[gi+1];
    float den = (tr-tl==0.f)?1.f:(tr-tl);
    float wq = (q-tl)/den;
    const float* y0 = g_ys + (gi*NB+b)*LATc;
    const float* y1 = g_ys + ((gi+1)*NB+b)*LATc;
    float* z = zs + w*66;
    float za = y0[lane]*(1.f-wq)+y1[lane]*wq;
    float zb = y0[lane+32]*(1.f-wq)+y1[lane+32]*wq;
    z[lane] = za; z[lane+32] = zb;
    out[1026 + b*64 + lane] = za;
    out[1026 + b*64 + lane + 32] = zb;
    if (lane == 0) z[64] = age[b];
    __syncwarp();
    float* a1 = a1s + w*128;
    #pragma unroll
    for (int jj = 0; jj < 4; jj++){
        int jx = lane + jj*32;
        float acc = bs1[jx];
        for (int k = 0; k < 65; k++) acc = fmaf(z[k], Ws1[k*128+jx], acc);
        a1[jx] = fmaxf(acc, 0.f);
    }
    __syncwarp();
    if (lane < 2){
        float acc = bs2[lane];
        for (int k = 0; k < 128; k++) acc = fmaf(a1[k], Ws2[k*2+lane], acc);
        out[b*2 + lane] = acc;
    }
}

// ---- K6: finalize scalars ----
__global__ void k6_final(float* __restrict__ out){
    __shared__ double sd[256]; __shared__ long long si[256]; __shared__ double kd[256];
    int tid = threadIdx.x;
    double s = 0; long long c = 0;
    for (int i = tid; i < 4096; i += 256){ s += (double)g_rpart[i]; c += g_ncnt[i]; }
    double ks = 0;
    for (int i = tid; i < NB; i += 256) ks += (double)g_klrow[i];
    sd[tid]=s; si[tid]=c; kd[tid]=ks; __syncthreads();
    for (int o=128;o>0;o>>=1){ if(tid<o){ sd[tid]+=sd[tid+o]; si[tid]+=si[tid+o]; kd[tid]+=kd[tid+o]; } __syncthreads(); }
    if (tid==0){
        double nn = (double)si[0];
        out[1024] = (nn > 0.0) ? (float)(sd[0] / (nn > 1.0 ? nn : 1.0)) : 0.f;
        out[1025] = (float)(-0.5 * (kd[0] / (double)NB));
    }
}

extern "C" void kernel_launch(void* const* d_in, const int* in_sizes, int n_in,
                              void* d_out, int out_size) {
    const float* obs = (const float*)d_in[0];
    const float* age = (const float*)d_in[1];
    const float* eps = (const float*)d_in[2];
    const float* Wih = (const float*)d_in[3];
    const float* Whh = (const float*)d_in[4];
    const float* bih = (const float*)d_in[5];
    const float* bhh = (const float*)d_in[6];
    const float* Wmu = (const float*)d_in[7];
    const float* bmu = (const float*)d_in[8];
    const float* Wlv = (const float*)d_in[9];
    const float* blv = (const float*)d_in[10];
    const float* W1  = (const float*)d_in[11];
    const float* b1  = (const float*)d_in[12];
    const float* W2  = (const float*)d_in[13];
    const float* b2  = (const float*)d_in[14];
    const float* W3  = (const float*)d_in[15];
    const float* b3  = (const float*)d_in[16];
    const float* Wo1 = (const float*)d_in[17];
    const float* bo1 = (const float*)d_in[18];
    const float* Wo2 = (const float*)d_in[19];
    const float* bo2 = (const float*)d_in[20];
    const float* Ws1 = (const float*)d_in[21];
    const float* bs1 = (const float*)d_in[22];
    const float* Ws2 = (const float*)d_in[23];
    const float* bs2 = (const float*)d_in[24];
    const void*  msk = d_in[25];
    const int*   tp  = (const int*)d_in[26];
    const int*   sq  = (const int*)d_in[27];
    float* out = (float*)d_out;

    cudaFuncSetAttribute(k1_ingemm, cudaFuncAttributeMaxDynamicSharedMemorySize, 116480);
    cudaFuncSetAttribute(k2_gru,    cudaFuncAttributeMaxDynamicSharedMemorySize, 210944);
    cudaFuncSetAttribute(k4_decode, cudaFuncAttributeMaxDynamicSharedMemorySize, 56576);

    k0_grid<<<1, 512>>>(tp, msk);
    k1_ingemm<<<512, 384, 116480>>>(obs, msk, tp, Wih, bih);
    k2_gru<<<128, 384, 210944>>>(Whh, bhh, Wmu, bmu, Wlv, blv, eps);
    k3_ode<<<128, 256>>>(W1, b1, W2, b2, W3, b3);
    k4_decode<<<4096, 256, 56576>>>(obs, msk, tp, Wo1, bo1, Wo2, bo2, sq);
    k5_eval<<<64, 256>>>(tp, sq, age, Ws1, bs1, Ws2, bs2, out);
    k6_final<<<1, 256>>>(out);
}